// round 6
// baseline (speedup 1.0000x reference)
#include <cuda_runtime.h>

#define BB 512
#define TT 512
#define IN_DIM 256
#define NJ 32          // 4 gates * 8 qubits
#define DTOT 264
#define ROWS (BB*TT)

// scratch: input projection, layout [row][q*4+g]  (q = qubit, g = gate f,i,g,o)
__device__ float g_proj[(size_t)ROWS * NJ];

typedef unsigned long long ull;

__device__ __forceinline__ ull pack2(float lo, float hi) {
    ull r;
    asm("mov.b64 %0, {%1, %2};" : "=l"(r) : "r"(__float_as_uint(lo)), "r"(__float_as_uint(hi)));
    return r;
}
__device__ __forceinline__ ull fma2(ull a, ull b, ull c) {
    ull d;
    asm("fma.rn.f32x2 %0, %1, %2, %3;" : "=l"(d) : "l"(a), "l"(b), "l"(c));
    return d;
}

// ---------------- GEMM: proj[r][q*4+g] = sum_k x[r][k] * W_g[q][k] ----------------
// 256 threads, 2 rows/thread (rows tid and tid+256 of a 512-row block slab).
__global__ void __launch_bounds__(256) gemm_kernel(
    const float* __restrict__ x,
    const float* __restrict__ Wf, const float* __restrict__ Wi,
    const float* __restrict__ Wg, const float* __restrict__ Wo)
{
    __shared__ __align__(16) float ws[IN_DIM * NJ];     // [k][q*4+g], 32 KB
    const int tid = threadIdx.x;

    for (int e = tid; e < IN_DIM * NJ; e += 256) {
        int k = e >> 5, j = e & 31;
        int q = j >> 2, g = j & 3;
        const float* Wp = (g == 0) ? Wf : (g == 1) ? Wi : (g == 2) ? Wg : Wo;
        ws[e] = Wp[q * DTOT + k];
    }
    __syncthreads();

    const size_t row0 = (size_t)blockIdx.x * 512 + tid;   // second row: row0 + 256
    const float4* x0 = reinterpret_cast<const float4*>(x + row0 * IN_DIM);
    const float4* x1 = reinterpret_cast<const float4*>(x + (row0 + 256) * IN_DIM);

    ull acc0[16], acc1[16];
    #pragma unroll
    for (int p = 0; p < 16; p++) { acc0[p] = 0ull; acc1[p] = 0ull; }

    #pragma unroll 4
    for (int k4 = 0; k4 < IN_DIM / 4; k4++) {
        float4 a = x0[k4];
        float4 b = x1[k4];
        float xa[4] = {a.x, a.y, a.z, a.w};
        float xb[4] = {b.x, b.y, b.z, b.w};
        #pragma unroll
        for (int kk = 0; kk < 4; kk++) {
            const double2* wv = reinterpret_cast<const double2*>(ws + (k4 * 4 + kk) * NJ);
            ull pa = pack2(xa[kk], xa[kk]);
            ull pb = pack2(xb[kk], xb[kk]);
            #pragma unroll
            for (int p4 = 0; p4 < 8; p4++) {
                double2 wd = wv[p4];
                ull w0 = (ull)__double_as_longlong(wd.x);
                ull w1 = (ull)__double_as_longlong(wd.y);
                acc0[2*p4]   = fma2(pa, w0, acc0[2*p4]);
                acc0[2*p4+1] = fma2(pa, w1, acc0[2*p4+1]);
                acc1[2*p4]   = fma2(pb, w0, acc1[2*p4]);
                acc1[2*p4+1] = fma2(pb, w1, acc1[2*p4+1]);
            }
        }
    }

    double2* o0 = reinterpret_cast<double2*>(g_proj + row0 * NJ);
    double2* o1 = reinterpret_cast<double2*>(g_proj + (row0 + 256) * NJ);
    #pragma unroll
    for (int p4 = 0; p4 < 8; p4++) {
        double2 v0, v1;
        v0.x = __longlong_as_double((long long)acc0[2*p4]);
        v0.y = __longlong_as_double((long long)acc0[2*p4+1]);
        v1.x = __longlong_as_double((long long)acc1[2*p4]);
        v1.y = __longlong_as_double((long long)acc1[2*p4+1]);
        o0[p4] = v0;
        o1[p4] = v1;
    }
}

// ---------------- activations: pure FMA / one RCP, valid on proven input ranges ----
// sigmoid(x), |x|<=1: 0.5 + x*poly(x^2), odd Taylor deg 9, err < 2.2e-6
__device__ __forceinline__ float sigp(float x) {
    float u = x * x;
    float p = fmaf(u, 2.1356922e-5f, -2.1081349e-4f);
    p = fmaf(u, p, 2.0833334e-3f);
    p = fmaf(u, p, -2.0833334e-2f);
    p = fmaf(u, p, 0.25f);
    return fmaf(x, p, 0.5f);
}
// tanh(x), |x|<=2.1: Pade x*(945+105u+u^2)/(945+420u+15u^2), err <= 7e-5
__device__ __forceinline__ float tanhp(float x) {
    float u = x * x;
    float N = fmaf(u, u + 105.0f, 945.0f);
    float D = fmaf(u, fmaf(15.0f, u, 420.0f), 945.0f);
    return __fdividef(x * N, D);
}

// ---------------- recurrence: one warp per 4 batches, lane = sub*8 + qubit --------
__global__ void __launch_bounds__(32) recur_kernel(
    const float* __restrict__ Wf, const float* __restrict__ bf,
    const float* __restrict__ Wi, const float* __restrict__ bi,
    const float* __restrict__ Wg, const float* __restrict__ bg,
    const float* __restrict__ Wo, const float* __restrict__ bo,
    const float* __restrict__ thetas, float* __restrict__ out)
{
    const unsigned FULL = 0xffffffffu;
    const int lane = threadIdx.x;
    const int q = lane & 7;
    const int wg = blockIdx.x * 4 + (lane >> 3);   // batch index

    const float* Wptr[4] = {Wf, Wi, Wg, Wo};
    const float* bptr[4] = {bf, bi, bg, bo};

    float wh[4][8];
    float bt[4];
    #pragma unroll
    for (int g = 0; g < 4; g++) {
        #pragma unroll
        for (int k = 0; k < 8; k++) wh[g][k] = Wptr[g][q * DTOT + IN_DIM + k];
        bt[g] = bptr[g][q] + thetas[g * 8 + q];
    }

    // loop-invariant select masks (no branches inside the loop)
    const bool ge1 = (q >= 1), ge2 = (q >= 2), ge4 = (q >= 4);
    const bool le6 = (q <= 6), le5 = (q <= 5), le3 = (q <= 3);
    const bool q0  = (q == 0);

    const float4* pr = reinterpret_cast<const float4*>(g_proj + (size_t)wg * TT * NJ) + q;
    // prefetch pipeline, distance 3 (stride per t = 8 float4)
    float4 pb0 = pr[0];
    float4 pb1 = pr[8];
    float4 pb2 = pr[16];

    float hx = 0.f, cx = 0.f;
    float* outp = out + (size_t)wg * TT * 8 + q;

    for (int t = 0; t < TT; t++) {
        float4 pin = pb0;
        pb0 = pb1; pb1 = pb2;
        int tn = t + 3; tn = (tn > TT - 1) ? (TT - 1) : tn;
        pb2 = pr[(size_t)tn * 8];

        // broadcast hidden state (independent shuffles)
        float hxv[8];
        #pragma unroll
        for (int k = 0; k < 8; k++) hxv[k] = __shfl_sync(FULL, hx, k, 8);

        float ang[4];
        ang[0] = pin.x + bt[0]; ang[1] = pin.y + bt[1];
        ang[2] = pin.z + bt[2]; ang[3] = pin.w + bt[3];
        #pragma unroll
        for (int g = 0; g < 4; g++) {
            float s0 = fmaf(wh[g][0], hxv[0], fmaf(wh[g][2], hxv[2],
                       fmaf(wh[g][4], hxv[4], wh[g][6] * hxv[6])));
            float s1 = fmaf(wh[g][1], hxv[1], fmaf(wh[g][3], hxv[3],
                       fmaf(wh[g][5], hxv[5], wh[g][7] * hxv[7])));
            ang[g] += s0 + s1;
        }

        // analytic circuit.  prefix p_k = prod_{0..k} c  (lane k>=1: m_k)
        //                    suffix s_0 = prod_{1..7} c  (lane 0:   m_0)
        float c[4], p[4], s[4];
        #pragma unroll
        for (int g = 0; g < 4; g++) {
            c[g] = __cosf(ang[g]);
            p[g] = c[g];
            s[g] = q0 ? 1.0f : c[g];
        }
        #pragma unroll
        for (int g = 0; g < 4; g++) {
            float v = __shfl_up_sync  (FULL, p[g], 1, 8);
            float w = __shfl_down_sync(FULL, s[g], 1, 8);
            p[g] *= ge1 ? v : 1.0f;
            s[g] *= le6 ? w : 1.0f;
        }
        #pragma unroll
        for (int g = 0; g < 4; g++) {
            float v = __shfl_up_sync  (FULL, p[g], 2, 8);
            float w = __shfl_down_sync(FULL, s[g], 2, 8);
            p[g] *= ge2 ? v : 1.0f;
            s[g] *= le5 ? w : 1.0f;
        }
        #pragma unroll
        for (int g = 0; g < 4; g++) {
            float v = __shfl_up_sync  (FULL, p[g], 4, 8);
            float w = __shfl_down_sync(FULL, s[g], 4, 8);
            p[g] *= ge4 ? v : 1.0f;
            s[g] *= le3 ? w : 1.0f;
        }
        float m[4];
        #pragma unroll
        for (int g = 0; g < 4; g++) m[g] = q0 ? s[g] : p[g];

        // gates: |m|<=1 guaranteed
        float f_ = sigp(m[0]);
        float i_ = sigp(m[1]);
        float gg = tanhp(m[2]);
        float o_ = sigp(m[3]);

        cx = fmaf(f_, cx, i_ * gg);          // |cx| <= 2.07
        hx = o_ * tanhp(cx);

        outp[(size_t)t * 8] = hx;
    }

    out[(size_t)BB * TT * 8 + (size_t)wg * 8 + q] = hx;                        // final hx
    out[(size_t)BB * TT * 8 + (size_t)BB * 8 + (size_t)wg * 8 + q] = cx;       // final cx
}

extern "C" void kernel_launch(void* const* d_in, const int* in_sizes, int n_in,
                              void* d_out, int out_size) {
    (void)in_sizes; (void)n_in; (void)out_size;
    const float* x  = (const float*)d_in[0];
    const float* Wf = (const float*)d_in[1]; const float* bf = (const float*)d_in[2];
    const float* Wi = (const float*)d_in[3]; const float* bi = (const float*)d_in[4];
    const float* Wg = (const float*)d_in[5]; const float* bg = (const float*)d_in[6];
    const float* Wo = (const float*)d_in[7]; const float* bo = (const float*)d_in[8];
    const float* th = (const float*)d_in[9];
    float* out = (float*)d_out;

    gemm_kernel<<<ROWS / 512, 256>>>(x, Wf, Wi, Wg, Wo);
    recur_kernel<<<BB / 4, 32>>>(Wf, bf, Wi, bi, Wg, bg, Wo, bo, th, out);
}

// round 7
// speedup vs baseline: 1.0089x; 1.0089x over previous
#include <cuda_runtime.h>

#define BB 512
#define TT 512
#define IN_DIM 256
#define NJ 32          // 4 gates * 8 qubits
#define DTOT 264
#define ROWS (BB*TT)

// scratch: input projection, layout [row][q*4+g]  (q = qubit, g = gate f,i,g,o)
__device__ float g_proj[(size_t)ROWS * NJ];

typedef unsigned long long ull;

__device__ __forceinline__ ull pack2(float lo, float hi) {
    ull r;
    asm("mov.b64 %0, {%1, %2};" : "=l"(r) : "r"(__float_as_uint(lo)), "r"(__float_as_uint(hi)));
    return r;
}
__device__ __forceinline__ ull fma2(ull a, ull b, ull c) {
    ull d;
    asm("fma.rn.f32x2 %0, %1, %2, %3;" : "=l"(d) : "l"(a), "l"(b), "l"(c));
    return d;
}

// ---------------- GEMM: proj[r][q*4+g] = sum_k x[r][k] * W_g[q][k] ----------------
// 256 threads, 4 rows/thread (rows tid + {0,256,512,768} of a 1024-row block slab).
__global__ void __launch_bounds__(256) gemm_kernel(
    const float* __restrict__ x,
    const float* __restrict__ Wf, const float* __restrict__ Wi,
    const float* __restrict__ Wg, const float* __restrict__ Wo)
{
    __shared__ __align__(16) float ws[IN_DIM * NJ];     // [k][q*4+g], 32 KB
    const int tid = threadIdx.x;

    for (int e = tid; e < IN_DIM * NJ; e += 256) {
        int k = e >> 5, j = e & 31;
        int q = j >> 2, g = j & 3;
        const float* Wp = (g == 0) ? Wf : (g == 1) ? Wi : (g == 2) ? Wg : Wo;
        ws[e] = Wp[q * DTOT + k];
    }
    __syncthreads();

    const size_t row0 = (size_t)blockIdx.x * 1024 + tid;   // rows row0 + r*256

    ull acc[64];
    #pragma unroll
    for (int p = 0; p < 64; p++) acc[p] = 0ull;

    for (int k4 = 0; k4 < IN_DIM / 4; k4++) {
        float xa[4][4];
        #pragma unroll
        for (int r = 0; r < 4; r++) {
            float4 v = *reinterpret_cast<const float4*>(
                x + (row0 + (size_t)r * 256) * IN_DIM + k4 * 4);
            xa[r][0] = v.x; xa[r][1] = v.y; xa[r][2] = v.z; xa[r][3] = v.w;
        }
        #pragma unroll
        for (int kk = 0; kk < 4; kk++) {
            const double2* wv = reinterpret_cast<const double2*>(ws + (k4 * 4 + kk) * NJ);
            ull pa[4];
            #pragma unroll
            for (int r = 0; r < 4; r++) pa[r] = pack2(xa[r][kk], xa[r][kk]);
            #pragma unroll
            for (int p4 = 0; p4 < 8; p4++) {
                double2 wd = wv[p4];
                ull w0 = (ull)__double_as_longlong(wd.x);
                ull w1 = (ull)__double_as_longlong(wd.y);
                #pragma unroll
                for (int r = 0; r < 4; r++) {
                    acc[r * 16 + 2 * p4]     = fma2(pa[r], w0, acc[r * 16 + 2 * p4]);
                    acc[r * 16 + 2 * p4 + 1] = fma2(pa[r], w1, acc[r * 16 + 2 * p4 + 1]);
                }
            }
        }
    }

    #pragma unroll
    for (int r = 0; r < 4; r++) {
        double2* o = reinterpret_cast<double2*>(g_proj + (row0 + (size_t)r * 256) * NJ);
        #pragma unroll
        for (int p4 = 0; p4 < 8; p4++) {
            double2 v;
            v.x = __longlong_as_double((long long)acc[r * 16 + 2 * p4]);
            v.y = __longlong_as_double((long long)acc[r * 16 + 2 * p4 + 1]);
            o[p4] = v;
        }
    }
}

// ---------------- activations: pure FMA / one RCP, valid on proven input ranges ----
// sigmoid(x), |x|<=1: 0.5 + x*poly(x^2), odd Taylor deg 9, err < 2.2e-6
__device__ __forceinline__ float sigp(float x) {
    float u = x * x;
    float p = fmaf(u, 2.1356922e-5f, -2.1081349e-4f);
    p = fmaf(u, p, 2.0833334e-3f);
    p = fmaf(u, p, -2.0833334e-2f);
    p = fmaf(u, p, 0.25f);
    return fmaf(x, p, 0.5f);
}
// tanh(x), |x|<=2.1: Pade x*(945+105u+u^2)/(945+420u+15u^2), err <= 7e-5
__device__ __forceinline__ float tanhp(float x) {
    float u = x * x;
    float N = fmaf(u, u + 105.0f, 945.0f);
    float D = fmaf(u, fmaf(15.0f, u, 420.0f), 945.0f);
    return __fdividef(x * N, D);
}

// ---------------- recurrence: one warp per 4 batches, lane = sub*8 + qubit --------
__global__ void __launch_bounds__(32) recur_kernel(
    const float* __restrict__ Wf, const float* __restrict__ bf,
    const float* __restrict__ Wi, const float* __restrict__ bi,
    const float* __restrict__ Wg, const float* __restrict__ bg,
    const float* __restrict__ Wo, const float* __restrict__ bo,
    const float* __restrict__ thetas, float* __restrict__ out)
{
    const unsigned FULL = 0xffffffffu;
    const int lane = threadIdx.x;
    const int q = lane & 7;
    const int wg = blockIdx.x * 4 + (lane >> 3);   // batch index

    const float* Wptr[4] = {Wf, Wi, Wg, Wo};
    const float* bptr[4] = {bf, bi, bg, bo};

    float wh[4][8];
    float bt[4];
    #pragma unroll
    for (int g = 0; g < 4; g++) {
        #pragma unroll
        for (int k = 0; k < 8; k++) wh[g][k] = Wptr[g][q * DTOT + IN_DIM + k];
        bt[g] = bptr[g][q] + thetas[g * 8 + q];
    }

    // loop-invariant lane predicates / source index (selects, no branches)
    const bool ge1 = (q >= 1), ge2 = (q >= 2), ge4 = (q >= 4);
    const bool q0  = (q == 0);
    const bool q7  = (q == 7);
    const int  src = q0 ? 7 : 0;   // merged-fixup shuffle source (within 8-lane group)

    const float4* pr = reinterpret_cast<const float4*>(g_proj + (size_t)wg * TT * NJ) + q;
    // prefetch pipeline, distance 3 (stride per t = 8 float4)
    float4 pb0 = pr[0];
    float4 pb1 = pr[8];
    float4 pb2 = pr[16];

    float hx = 0.f, cx = 0.f;
    float* outp = out + (size_t)wg * TT * 8 + q;

    for (int t = 0; t < TT; t++) {
        float4 pin = pb0;
        pb0 = pb1; pb1 = pb2;
        int tn = t + 3; tn = (tn > TT - 1) ? (TT - 1) : tn;
        pb2 = pr[(size_t)tn * 8];

        // broadcast hidden state (independent shuffles)
        float hxv[8];
        #pragma unroll
        for (int k = 0; k < 8; k++) hxv[k] = __shfl_sync(FULL, hx, k, 8);

        float ang[4];
        ang[0] = pin.x + bt[0]; ang[1] = pin.y + bt[1];
        ang[2] = pin.z + bt[2]; ang[3] = pin.w + bt[3];
        #pragma unroll
        for (int g = 0; g < 4; g++) {
            float s0 = fmaf(wh[g][0], hxv[0], fmaf(wh[g][2], hxv[2],
                       fmaf(wh[g][4], hxv[4], wh[g][6] * hxv[6])));
            float s1 = fmaf(wh[g][1], hxv[1], fmaf(wh[g][3], hxv[3],
                       fmaf(wh[g][5], hxv[5], wh[g][7] * hxv[7])));
            ang[g] += s0 + s1;
        }

        // analytic circuit: masked up-scan gives p_q = prod_{1..q} c (lane0 seeded 1)
        float c[4], p[4];
        #pragma unroll
        for (int g = 0; g < 4; g++) {
            c[g] = __cosf(ang[g]);
            p[g] = q0 ? 1.0f : c[g];
        }
        #pragma unroll
        for (int g = 0; g < 4; g++) {
            float v = __shfl_up_sync(FULL, p[g], 1, 8);
            p[g] *= ge1 ? v : 1.0f;
        }
        #pragma unroll
        for (int g = 0; g < 4; g++) {
            float v = __shfl_up_sync(FULL, p[g], 2, 8);
            p[g] *= ge2 ? v : 1.0f;
        }
        #pragma unroll
        for (int g = 0; g < 4; g++) {
            float v = __shfl_up_sync(FULL, p[g], 4, 8);
            p[g] *= ge4 ? v : 1.0f;
        }
        // merged fixup: lane0 reads p_7 (= m_0); lanes 1..7 read c_0; one shuffle/gate
        float m[4];
        #pragma unroll
        for (int g = 0; g < 4; g++) {
            float z = q7 ? p[g] : c[g];
            float w = __shfl_sync(FULL, z, src, 8);
            m[g] = q0 ? w : w * p[g];
        }

        // gates: |m|<=1 guaranteed
        float f_ = sigp(m[0]);
        float i_ = sigp(m[1]);
        float gg = tanhp(m[2]);
        float o_ = sigp(m[3]);

        cx = fmaf(f_, cx, i_ * gg);          // |cx| <= 2.07
        hx = o_ * tanhp(cx);

        outp[(size_t)t * 8] = hx;
    }

    out[(size_t)BB * TT * 8 + (size_t)wg * 8 + q] = hx;                        // final hx
    out[(size_t)BB * TT * 8 + (size_t)BB * 8 + (size_t)wg * 8 + q] = cx;       // final cx
}

extern "C" void kernel_launch(void* const* d_in, const int* in_sizes, int n_in,
                              void* d_out, int out_size) {
    (void)in_sizes; (void)n_in; (void)out_size;
    const float* x  = (const float*)d_in[0];
    const float* Wf = (const float*)d_in[1]; const float* bf = (const float*)d_in[2];
    const float* Wi = (const float*)d_in[3]; const float* bi = (const float*)d_in[4];
    const float* Wg = (const float*)d_in[5]; const float* bg = (const float*)d_in[6];
    const float* Wo = (const float*)d_in[7]; const float* bo = (const float*)d_in[8];
    const float* th = (const float*)d_in[9];
    float* out = (float*)d_out;

    gemm_kernel<<<ROWS / 1024, 256>>>(x, Wf, Wi, Wg, Wo);
    recur_kernel<<<BB / 4, 32>>>(Wf, bf, Wi, bi, Wg, bg, Wo, bo, th, out);
}